// round 1
// baseline (speedup 1.0000x reference)
#include <cuda_runtime.h>
#include <math.h>

#define BB 2
#define LL 1024
#define MTOK 2048           // B*L
#define DMODEL 768
#define DINNER 1536
#define DSTATE 16
#define DTRANK 48
#define DBC_W  80           // DTRANK + 2*DSTATE
#define DCONV 4
#define VOCABN 32000
#define NLAYERS 2

// ---------------- scratch (device globals; no allocations allowed) ----------
__device__ float g_h[MTOK * DMODEL];
__device__ float g_xn[MTOK * DMODEL];
__device__ float g_xz[MTOK * 2 * DINNER];
__device__ float g_xa[MTOK * DINNER];
__device__ float g_dbc[MTOK * DBC_W];
__device__ float g_delta[MTOK * DINNER];
__device__ float g_y[MTOK * DINNER];

// ---------------- small helpers --------------------------------------------
__device__ __forceinline__ float softplusf(float x) {
    return (x > 20.f) ? x : log1pf(__expf(x));
}
__device__ __forceinline__ float siluf(float x) {
    return x / (1.f + __expf(-x));
}

// ---------------- embedding gather -----------------------------------------
__global__ void embed_kernel(const int* __restrict__ tok,
                             const float* __restrict__ W,
                             float* __restrict__ out) {
    int m = blockIdx.x;
    int t = tok[m];
    const float* src = W + (size_t)t * DMODEL;
    float* dst = out + (size_t)m * DMODEL;
    for (int i = threadIdx.x; i < DMODEL; i += blockDim.x) dst[i] = src[i];
}

// ---------------- rmsnorm ---------------------------------------------------
__global__ void rmsnorm_kernel(const float* __restrict__ x,
                               const float* __restrict__ w,
                               float* __restrict__ out) {
    int m = blockIdx.x;
    const float* row = x + (size_t)m * DMODEL;
    float s = 0.f;
    for (int i = threadIdx.x; i < DMODEL; i += blockDim.x) {
        float v = row[i];
        s += v * v;
    }
    for (int o = 16; o > 0; o >>= 1) s += __shfl_xor_sync(0xffffffffu, s, o);
    __shared__ float red[8];
    __shared__ float scale_s;
    int warp = threadIdx.x >> 5, lane = threadIdx.x & 31;
    if (lane == 0) red[warp] = s;
    __syncthreads();
    if (threadIdx.x == 0) {
        float t = 0.f;
        int nw = (blockDim.x + 31) >> 5;
        for (int i = 0; i < nw; i++) t += red[i];
        scale_s = rsqrtf(t / (float)DMODEL + 1e-5f);
    }
    __syncthreads();
    float scale = scale_s;
    for (int i = threadIdx.x; i < DMODEL; i += blockDim.x)
        out[(size_t)m * DMODEL + i] = row[i] * scale * w[i];
}

// ---------------- tiled SGEMM: C[M,N] = A[M,K] * B[N,K]^T  (NT layout) ------
// 128x128 block tile, BK=8, 8x8 per-thread tile, 256 threads.
#define GBM 128
#define GBN 128
#define GBK 8
#define GTM 8
#define GTN 8

#define EPI_NONE 0
#define EPI_BIAS 1
#define EPI_BIAS_SOFTPLUS 2
#define EPI_RESADD 3

template <int EPI>
__global__ __launch_bounds__(256) void sgemm_nt(
    int M, int N, int K,
    const float* __restrict__ A, int lda,
    const float* __restrict__ B, int ldb,
    float* __restrict__ C, int ldc,
    const float* __restrict__ bias,
    const float* __restrict__ res) {
    __shared__ float As[GBK][GBM];
    __shared__ float Bs[GBK][GBN];

    const int tid = threadIdx.x;
    const int tcol = tid & 15;   // 0..15
    const int trow = tid >> 4;   // 0..15

    const int mBase = blockIdx.y * GBM;
    const int nBase = blockIdx.x * GBN;

    const float* Ab = A + (size_t)mBase * lda;
    const float* Bb = B + (size_t)nBase * ldb;

    const int lrow = tid >> 1;        // 0..127
    const int lcol = (tid & 1) * 4;   // 0 or 4

    const bool aRowValid = (mBase + lrow) < M;
    const bool bRowValid = (nBase + lrow) < N;

    float acc[GTM][GTN];
#pragma unroll
    for (int i = 0; i < GTM; i++)
#pragma unroll
        for (int j = 0; j < GTN; j++) acc[i][j] = 0.f;

    for (int k0 = 0; k0 < K; k0 += GBK) {
        float4 a4 = make_float4(0.f, 0.f, 0.f, 0.f);
        float4 b4 = make_float4(0.f, 0.f, 0.f, 0.f);
        if (aRowValid && (k0 + lcol) < K)
            a4 = *(const float4*)(Ab + (size_t)lrow * lda + k0 + lcol);
        if (bRowValid && (k0 + lcol) < K)
            b4 = *(const float4*)(Bb + (size_t)lrow * ldb + k0 + lcol);
        As[lcol + 0][lrow] = a4.x;
        As[lcol + 1][lrow] = a4.y;
        As[lcol + 2][lrow] = a4.z;
        As[lcol + 3][lrow] = a4.w;
        Bs[lcol + 0][lrow] = b4.x;
        Bs[lcol + 1][lrow] = b4.y;
        Bs[lcol + 2][lrow] = b4.z;
        Bs[lcol + 3][lrow] = b4.w;
        __syncthreads();

#pragma unroll
        for (int k = 0; k < GBK; k++) {
            float regM[GTM], regN[GTN];
#pragma unroll
            for (int i = 0; i < GTM; i++) regM[i] = As[k][trow * GTM + i];
#pragma unroll
            for (int j = 0; j < GTN; j++) regN[j] = Bs[k][tcol * GTN + j];
#pragma unroll
            for (int i = 0; i < GTM; i++)
#pragma unroll
                for (int j = 0; j < GTN; j++)
                    acc[i][j] = fmaf(regM[i], regN[j], acc[i][j]);
        }
        __syncthreads();
    }

#pragma unroll
    for (int i = 0; i < GTM; i++) {
        int row = mBase + trow * GTM + i;
        if (row >= M) continue;
#pragma unroll
        for (int j = 0; j < GTN; j++) {
            int col = nBase + tcol * GTN + j;
            if (col >= N) continue;
            float v = acc[i][j];
            if (EPI == EPI_BIAS) v += bias[col];
            if (EPI == EPI_BIAS_SOFTPLUS) v = softplusf(v + bias[col]);
            if (EPI == EPI_RESADD) v += res[(size_t)row * ldc + col];
            C[(size_t)row * ldc + col] = v;
        }
    }
}

// ---------------- causal depthwise conv (width 4) + bias + SiLU -------------
__global__ void conv_silu_kernel(const float* __restrict__ xz,
                                 const float* __restrict__ cw,
                                 const float* __restrict__ cb,
                                 float* __restrict__ xa) {
    int idx = blockIdx.x * blockDim.x + threadIdx.x;
    if (idx >= MTOK * DINNER) return;
    int e = idx % DINNER;
    int m = idx / DINNER;
    int l = m % LL;
    float acc = cb[e];
#pragma unroll
    for (int j = 0; j < DCONV; j++) {
        int lj = l + j - (DCONV - 1);
        if (lj >= 0)
            acc = fmaf(xz[(size_t)(m + j - (DCONV - 1)) * (2 * DINNER) + e],
                       cw[e * DCONV + j], acc);
    }
    xa[idx] = siluf(acc);
}

// ---------------- selective scan + D*xa + silu(z) gate -----------------------
// One warp handles two channels e (half-warps), 16 lanes own the 16 states n.
__global__ void scan_kernel(const float* __restrict__ delta,
                            const float* __restrict__ dbc,
                            const float* __restrict__ xa,
                            const float* __restrict__ xz,
                            const float* __restrict__ A_log,
                            const float* __restrict__ Dp,
                            float* __restrict__ y) {
    int w = (blockIdx.x * blockDim.x + threadIdx.x) >> 5;
    int lane = threadIdx.x & 31;
    if (w >= BB * (DINNER / 2)) return;
    int b = w / (DINNER / 2);
    int ep = w % (DINNER / 2);
    int half = lane >> 4;
    int n = lane & 15;
    int e = ep * 2 + half;

    float A_ne = -__expf(A_log[e * DSTATE + n]);
    float Dv = Dp[e];
    float h = 0.f;
    int m0 = b * LL;
    for (int l = 0; l < LL; l++) {
        int m = m0 + l;
        float dlt = delta[(size_t)m * DINNER + e];
        float xav = xa[(size_t)m * DINNER + e];
        float Bv = dbc[(size_t)m * DBC_W + DTRANK + n];
        float Cv = dbc[(size_t)m * DBC_W + DTRANK + DSTATE + n];
        float dA = __expf(dlt * A_ne);
        h = fmaf(dA, h, dlt * Bv * xav);
        float p = h * Cv;
        p += __shfl_xor_sync(0xffffffffu, p, 8);
        p += __shfl_xor_sync(0xffffffffu, p, 4);
        p += __shfl_xor_sync(0xffffffffu, p, 2);
        p += __shfl_xor_sync(0xffffffffu, p, 1);
        if (n == 0) {
            float yv = p + Dv * xav;
            float zv = xz[(size_t)m * (2 * DINNER) + DINNER + e];
            y[(size_t)m * DINNER + e] = yv * siluf(zv);
        }
    }
}

// ---------------- launch ------------------------------------------------------
extern "C" void kernel_launch(void* const* d_in, const int* in_sizes, int n_in,
                              void* d_out, int out_size) {
    const int* x            = (const int*)d_in[0];
    const float* embed_W    = (const float*)d_in[1];
    const float* norm_w     = (const float*)d_in[2];
    const float* in_proj_w  = (const float*)d_in[3];
    const float* conv_w     = (const float*)d_in[4];
    const float* conv_b     = (const float*)d_in[5];
    const float* x_proj_w   = (const float*)d_in[6];
    const float* dt_proj_w  = (const float*)d_in[7];
    const float* dt_proj_b  = (const float*)d_in[8];
    const float* A_log      = (const float*)d_in[9];
    const float* D_param    = (const float*)d_in[10];
    const float* out_proj_w = (const float*)d_in[11];
    const float* normf_w    = (const float*)d_in[12];
    const float* head_w     = (const float*)d_in[13];
    const float* head_b     = (const float*)d_in[14];
    float* logits           = (float*)d_out;

    float *hbuf, *xn, *xz, *xa, *dbc, *delta, *ybuf;
    cudaGetSymbolAddress((void**)&hbuf,  g_h);
    cudaGetSymbolAddress((void**)&xn,    g_xn);
    cudaGetSymbolAddress((void**)&xz,    g_xz);
    cudaGetSymbolAddress((void**)&xa,    g_xa);
    cudaGetSymbolAddress((void**)&dbc,   g_dbc);
    cudaGetSymbolAddress((void**)&delta, g_delta);
    cudaGetSymbolAddress((void**)&ybuf,  g_y);

    // embed
    embed_kernel<<<MTOK, 256>>>(x, embed_W, hbuf);

    for (int i = 0; i < NLAYERS; i++) {
        const float* nw  = norm_w     + (size_t)i * DMODEL;
        const float* iw  = in_proj_w  + (size_t)i * 2 * DINNER * DMODEL;
        const float* cw  = conv_w     + (size_t)i * DINNER * DCONV;
        const float* cb  = conv_b     + (size_t)i * DINNER;
        const float* xpw = x_proj_w   + (size_t)i * DBC_W * DINNER;
        const float* dtw = dt_proj_w  + (size_t)i * DINNER * DTRANK;
        const float* dtb = dt_proj_b  + (size_t)i * DINNER;
        const float* al  = A_log      + (size_t)i * DINNER * DSTATE;
        const float* dp  = D_param    + (size_t)i * DINNER;
        const float* ow  = out_proj_w + (size_t)i * DMODEL * DINNER;

        // xn = rmsnorm(h)
        rmsnorm_kernel<<<MTOK, 256>>>(hbuf, nw, xn);

        // xz[2048,3072] = xn[2048,768] @ iw[3072,768]^T
        {
            dim3 grid((2 * DINNER + GBN - 1) / GBN, (MTOK + GBM - 1) / GBM);
            sgemm_nt<EPI_NONE><<<grid, 256>>>(MTOK, 2 * DINNER, DMODEL,
                                              xn, DMODEL, iw, DMODEL,
                                              xz, 2 * DINNER, nullptr, nullptr);
        }

        // xa = silu(causal depthwise conv(xz[:, :1536]) + cb)
        conv_silu_kernel<<<(MTOK * DINNER + 255) / 256, 256>>>(xz, cw, cb, xa);

        // dbc[2048,80] = xa @ xpw[80,1536]^T
        {
            dim3 grid((DBC_W + GBN - 1) / GBN, (MTOK + GBM - 1) / GBM);
            sgemm_nt<EPI_NONE><<<grid, 256>>>(MTOK, DBC_W, DINNER,
                                              xa, DINNER, xpw, DINNER,
                                              dbc, DBC_W, nullptr, nullptr);
        }

        // delta[2048,1536] = softplus(dbc[:, :48] @ dtw[1536,48]^T + dtb)
        {
            dim3 grid((DINNER + GBN - 1) / GBN, (MTOK + GBM - 1) / GBM);
            sgemm_nt<EPI_BIAS_SOFTPLUS><<<grid, 256>>>(MTOK, DINNER, DTRANK,
                                                       dbc, DBC_W, dtw, DTRANK,
                                                       delta, DINNER, dtb, nullptr);
        }

        // y = selective_scan(...) + D*xa, gated by silu(z)
        {
            int warps = BB * (DINNER / 2);              // 1536
            int blocks = (warps * 32 + 255) / 256;      // 192
            scan_kernel<<<blocks, 256>>>(delta, dbc, xa, xz, al, dp, ybuf);
        }

        // h += y @ ow[768,1536]^T   (residual fused in epilogue)
        {
            dim3 grid((DMODEL + GBN - 1) / GBN, (MTOK + GBM - 1) / GBM);
            sgemm_nt<EPI_RESADD><<<grid, 256>>>(MTOK, DMODEL, DINNER,
                                                ybuf, DINNER, ow, DINNER,
                                                hbuf, DMODEL, nullptr, hbuf);
        }
    }

    // final norm
    rmsnorm_kernel<<<MTOK, 256>>>(hbuf, normf_w, xn);

    // logits[2048,32000] = xn @ head_w[32000,768]^T + head_b
    {
        dim3 grid((VOCABN + GBN - 1) / GBN, (MTOK + GBM - 1) / GBM);
        sgemm_nt<EPI_BIAS><<<grid, 256>>>(MTOK, VOCABN, DMODEL,
                                          xn, DMODEL, head_w, DMODEL,
                                          logits, VOCABN, head_b, nullptr);
    }

    (void)in_sizes; (void)n_in; (void)out_size;
}

// round 2
// speedup vs baseline: 1.9586x; 1.9586x over previous
#include <cuda_runtime.h>
#include <math.h>
#include <stdint.h>

#define BB 2
#define LL 1024
#define MTOK 2048           // B*L
#define DMODEL 768
#define DINNER 1536
#define DSTATE 16
#define DTRANK 48
#define DBC_W  80           // DTRANK + 2*DSTATE
#define DCONV 4
#define VOCABN 32000
#define NLAYERS 2

// ---------------- scratch (device globals; no allocations allowed) ----------
__device__ float g_h[MTOK * DMODEL];
__device__ float g_xn[MTOK * DMODEL];
__device__ float g_xz[MTOK * 2 * DINNER];
__device__ float g_xa[MTOK * DINNER];
__device__ float g_dbc[MTOK * DBC_W];
__device__ float g_delta[MTOK * DINNER];
__device__ float g_y[MTOK * DINNER];

// ---------------- small helpers --------------------------------------------
__device__ __forceinline__ float softplusf(float x) {
    return (x > 20.f) ? x : log1pf(__expf(x));
}
__device__ __forceinline__ float siluf(float x) {
    return x / (1.f + __expf(-x));
}
__device__ __forceinline__ uint32_t f2tf32(float x) {
    uint32_t r;
    asm("cvt.rna.tf32.f32 %0, %1;" : "=r"(r) : "f"(x));
    return r;
}
__device__ __forceinline__ void cpa16(void* smem_dst, const void* gmem_src) {
    uint32_t sa = (uint32_t)__cvta_generic_to_shared(smem_dst);
    asm volatile("cp.async.cg.shared.global [%0], [%1], 16;" :: "r"(sa), "l"(gmem_src));
}
__device__ __forceinline__ void cpa_commit() {
    asm volatile("cp.async.commit_group;");
}

// ---------------- embedding gather -----------------------------------------
__global__ void embed_kernel(const int* __restrict__ tok,
                             const float* __restrict__ W,
                             float* __restrict__ out) {
    int m = blockIdx.x;
    int t = tok[m];
    const float* src = W + (size_t)t * DMODEL;
    float* dst = out + (size_t)m * DMODEL;
    for (int i = threadIdx.x; i < DMODEL; i += blockDim.x) dst[i] = src[i];
}

// ---------------- rmsnorm ---------------------------------------------------
__global__ void rmsnorm_kernel(const float* __restrict__ x,
                               const float* __restrict__ w,
                               float* __restrict__ out) {
    int m = blockIdx.x;
    const float* row = x + (size_t)m * DMODEL;
    float s = 0.f;
    for (int i = threadIdx.x; i < DMODEL; i += blockDim.x) {
        float v = row[i];
        s += v * v;
    }
    for (int o = 16; o > 0; o >>= 1) s += __shfl_xor_sync(0xffffffffu, s, o);
    __shared__ float red[8];
    __shared__ float scale_s;
    int warp = threadIdx.x >> 5, lane = threadIdx.x & 31;
    if (lane == 0) red[warp] = s;
    __syncthreads();
    if (threadIdx.x == 0) {
        float t = 0.f;
        int nw = (blockDim.x + 31) >> 5;
        for (int i = 0; i < nw; i++) t += red[i];
        scale_s = rsqrtf(t / (float)DMODEL + 1e-5f);
    }
    __syncthreads();
    float scale = scale_s;
    for (int i = threadIdx.x; i < DMODEL; i += blockDim.x)
        out[(size_t)m * DMODEL + i] = row[i] * scale * w[i];
}

// =============================================================================
// TF32 tensor-core GEMM: C[M,N] = A[M,K] * B[N,K]^T (both K-contiguous)
// 128x128 CTA tile, BK=16, 128 threads = 4 warps of 64x64.
// cp.async double-buffered smem. Requires M%128==0, N%128==0, K%16==0.
// smem layout [row][BK+4] -> conflict-free cp.async STS and fragment LDS.
// =============================================================================
#define TBM 128
#define TBN 128
#define TBK 16
#define TPAD 4
#define TKS (TBK + TPAD)   // 20

#define EPI_NONE 0
#define EPI_BIAS 1
#define EPI_BIAS_SOFTPLUS 2
#define EPI_RESADD 3

template <int EPI>
__global__ __launch_bounds__(128) void tf32_gemm_nt(
    int M, int N, int K,
    const float* __restrict__ A, int lda,
    const float* __restrict__ B, int ldb,
    float* __restrict__ C, int ldc,
    const float* __restrict__ bias,
    const float* __restrict__ res) {
    __shared__ float As[2][TBM][TKS];
    __shared__ float Bs[2][TBN][TKS];

    const int tid  = threadIdx.x;
    const int warp = tid >> 5;
    const int lane = tid & 31;
    const int wm = (warp >> 1) * 64;   // warp m-offset within CTA tile
    const int wn = (warp & 1) * 64;    // warp n-offset
    const int g = lane >> 2;           // groupID 0..7
    const int t = lane & 3;            // thread-in-group 0..3

    const int mBase = blockIdx.y * TBM;
    const int nBase = blockIdx.x * TBN;

    const float* Abase = A + (size_t)mBase * lda;
    const float* Bbase = B + (size_t)nBase * ldb;

    // load mapping: 128 threads, per tile each thread cp.asyncs 4 A-rows + 4 B-rows
    const int lr = tid >> 2;           // 0..31
    const int lk = (tid & 3) * 4;      // 0,4,8,12

    float acc[4][8][4];
#pragma unroll
    for (int mi = 0; mi < 4; mi++)
#pragma unroll
        for (int ni = 0; ni < 8; ni++)
#pragma unroll
            for (int c = 0; c < 4; c++) acc[mi][ni][c] = 0.f;

    const int T = K / TBK;

    // issue tile 0
    {
#pragma unroll
        for (int i = 0; i < 4; i++) {
            int row = lr + i * 32;
            cpa16(&As[0][row][lk], Abase + (size_t)row * lda + lk);
            cpa16(&Bs[0][row][lk], Bbase + (size_t)row * ldb + lk);
        }
        cpa_commit();
    }

    for (int kt = 0; kt < T; kt++) {
        if (kt + 1 < T) {
            int k0 = (kt + 1) * TBK;
            int buf = (kt + 1) & 1;
#pragma unroll
            for (int i = 0; i < 4; i++) {
                int row = lr + i * 32;
                cpa16(&As[buf][row][lk], Abase + (size_t)row * lda + k0 + lk);
                cpa16(&Bs[buf][row][lk], Bbase + (size_t)row * ldb + k0 + lk);
            }
            cpa_commit();
            asm volatile("cp.async.wait_group 1;");
        } else {
            asm volatile("cp.async.wait_group 0;");
        }
        __syncthreads();

        const int buf = kt & 1;
#pragma unroll
        for (int ks = 0; ks < 2; ks++) {
            const int kb = ks * 8;
            uint32_t af[4][4];
            uint32_t bf[8][2];
#pragma unroll
            for (int mi = 0; mi < 4; mi++) {
                int m = wm + mi * 16;
                af[mi][0] = f2tf32(As[buf][m + g][kb + t]);
                af[mi][1] = f2tf32(As[buf][m + g + 8][kb + t]);
                af[mi][2] = f2tf32(As[buf][m + g][kb + t + 4]);
                af[mi][3] = f2tf32(As[buf][m + g + 8][kb + t + 4]);
            }
#pragma unroll
            for (int ni = 0; ni < 8; ni++) {
                int n = wn + ni * 8;
                bf[ni][0] = f2tf32(Bs[buf][n + g][kb + t]);
                bf[ni][1] = f2tf32(Bs[buf][n + g][kb + t + 4]);
            }
#pragma unroll
            for (int mi = 0; mi < 4; mi++)
#pragma unroll
                for (int ni = 0; ni < 8; ni++) {
                    asm volatile(
                        "mma.sync.aligned.m16n8k8.row.col.f32.tf32.tf32.f32 "
                        "{%0,%1,%2,%3}, {%4,%5,%6,%7}, {%8,%9}, {%0,%1,%2,%3};"
                        : "+f"(acc[mi][ni][0]), "+f"(acc[mi][ni][1]),
                          "+f"(acc[mi][ni][2]), "+f"(acc[mi][ni][3])
                        : "r"(af[mi][0]), "r"(af[mi][1]), "r"(af[mi][2]), "r"(af[mi][3]),
                          "r"(bf[ni][0]), "r"(bf[ni][1]));
                }
        }
        __syncthreads();
    }

    // epilogue
#pragma unroll
    for (int mi = 0; mi < 4; mi++) {
        int row = mBase + wm + mi * 16 + g;
#pragma unroll
        for (int ni = 0; ni < 8; ni++) {
            int col = nBase + wn + ni * 8 + 2 * t;
            float v0 = acc[mi][ni][0], v1 = acc[mi][ni][1];
            float v2 = acc[mi][ni][2], v3 = acc[mi][ni][3];
            if (EPI == EPI_BIAS) {
                float2 bv = *(const float2*)(bias + col);
                v0 += bv.x; v1 += bv.y; v2 += bv.x; v3 += bv.y;
            }
            if (EPI == EPI_BIAS_SOFTPLUS) {
                float2 bv = *(const float2*)(bias + col);
                v0 = softplusf(v0 + bv.x); v1 = softplusf(v1 + bv.y);
                v2 = softplusf(v2 + bv.x); v3 = softplusf(v3 + bv.y);
            }
            if (EPI == EPI_RESADD) {
                float2 r0 = *(const float2*)(res + (size_t)row * ldc + col);
                float2 r1 = *(const float2*)(res + (size_t)(row + 8) * ldc + col);
                v0 += r0.x; v1 += r0.y; v2 += r1.x; v3 += r1.y;
            }
            *(float2*)(C + (size_t)row * ldc + col) = make_float2(v0, v1);
            *(float2*)(C + (size_t)(row + 8) * ldc + col) = make_float2(v2, v3);
        }
    }
}

// ---------------- SIMT SGEMM (kept for N=80 dbc projection) -----------------
#define GBM 128
#define GBN 128
#define GBK 8
#define GTM 8
#define GTN 8

__global__ __launch_bounds__(256) void sgemm_nt_simt(
    int M, int N, int K,
    const float* __restrict__ A, int lda,
    const float* __restrict__ B, int ldb,
    float* __restrict__ C, int ldc) {
    __shared__ float As[GBK][GBM];
    __shared__ float Bs[GBK][GBN];

    const int tid = threadIdx.x;
    const int tcol = tid & 15;
    const int trow = tid >> 4;

    const int mBase = blockIdx.y * GBM;
    const int nBase = blockIdx.x * GBN;

    const float* Ab = A + (size_t)mBase * lda;
    const float* Bb = B + (size_t)nBase * ldb;

    const int lrow = tid >> 1;
    const int lcol = (tid & 1) * 4;

    const bool aRowValid = (mBase + lrow) < M;
    const bool bRowValid = (nBase + lrow) < N;

    float acc[GTM][GTN];
#pragma unroll
    for (int i = 0; i < GTM; i++)
#pragma unroll
        for (int j = 0; j < GTN; j++) acc[i][j] = 0.f;

    for (int k0 = 0; k0 < K; k0 += GBK) {
        float4 a4 = make_float4(0.f, 0.f, 0.f, 0.f);
        float4 b4 = make_float4(0.f, 0.f, 0.f, 0.f);
        if (aRowValid && (k0 + lcol) < K)
            a4 = *(const float4*)(Ab + (size_t)lrow * lda + k0 + lcol);
        if (bRowValid && (k0 + lcol) < K)
            b4 = *(const float4*)(Bb + (size_t)lrow * ldb + k0 + lcol);
        As[lcol + 0][lrow] = a4.x; As[lcol + 1][lrow] = a4.y;
        As[lcol + 2][lrow] = a4.z; As[lcol + 3][lrow] = a4.w;
        Bs[lcol + 0][lrow] = b4.x; Bs[lcol + 1][lrow] = b4.y;
        Bs[lcol + 2][lrow] = b4.z; Bs[lcol + 3][lrow] = b4.w;
        __syncthreads();

#pragma unroll
        for (int k = 0; k < GBK; k++) {
            float regM[GTM], regN[GTN];
#pragma unroll
            for (int i = 0; i < GTM; i++) regM[i] = As[k][trow * GTM + i];
#pragma unroll
            for (int j = 0; j < GTN; j++) regN[j] = Bs[k][tcol * GTN + j];
#pragma unroll
            for (int i = 0; i < GTM; i++)
#pragma unroll
                for (int j = 0; j < GTN; j++)
                    acc[i][j] = fmaf(regM[i], regN[j], acc[i][j]);
        }
        __syncthreads();
    }

#pragma unroll
    for (int i = 0; i < GTM; i++) {
        int row = mBase + trow * GTM + i;
        if (row >= M) continue;
#pragma unroll
        for (int j = 0; j < GTN; j++) {
            int col = nBase + tcol * GTN + j;
            if (col >= N) continue;
            C[(size_t)row * ldc + col] = acc[i][j];
        }
    }
}

// ---------------- causal depthwise conv (width 4) + bias + SiLU -------------
__global__ void conv_silu_kernel(const float* __restrict__ xz,
                                 const float* __restrict__ cw,
                                 const float* __restrict__ cb,
                                 float* __restrict__ xa) {
    int idx = blockIdx.x * blockDim.x + threadIdx.x;
    if (idx >= MTOK * DINNER) return;
    int e = idx % DINNER;
    int m = idx / DINNER;
    int l = m % LL;
    float acc = cb[e];
#pragma unroll
    for (int j = 0; j < DCONV; j++) {
        int lj = l + j - (DCONV - 1);
        if (lj >= 0)
            acc = fmaf(xz[(size_t)(m + j - (DCONV - 1)) * (2 * DINNER) + e],
                       cw[e * DCONV + j], acc);
    }
    xa[idx] = siluf(acc);
}

// ---------------- selective scan + D*xa + silu(z) gate -----------------------
__global__ void scan_kernel(const float* __restrict__ delta,
                            const float* __restrict__ dbc,
                            const float* __restrict__ xa,
                            const float* __restrict__ xz,
                            const float* __restrict__ A_log,
                            const float* __restrict__ Dp,
                            float* __restrict__ y) {
    int w = (blockIdx.x * blockDim.x + threadIdx.x) >> 5;
    int lane = threadIdx.x & 31;
    if (w >= BB * (DINNER / 2)) return;
    int b = w / (DINNER / 2);
    int ep = w % (DINNER / 2);
    int half = lane >> 4;
    int n = lane & 15;
    int e = ep * 2 + half;

    float A_ne = -__expf(A_log[e * DSTATE + n]);
    float Dv = Dp[e];
    float h = 0.f;
    int m0 = b * LL;
    for (int l = 0; l < LL; l++) {
        int m = m0 + l;
        float dlt = delta[(size_t)m * DINNER + e];
        float xav = xa[(size_t)m * DINNER + e];
        float Bv = dbc[(size_t)m * DBC_W + DTRANK + n];
        float Cv = dbc[(size_t)m * DBC_W + DTRANK + DSTATE + n];
        float dA = __expf(dlt * A_ne);
        h = fmaf(dA, h, dlt * Bv * xav);
        float p = h * Cv;
        p += __shfl_xor_sync(0xffffffffu, p, 8);
        p += __shfl_xor_sync(0xffffffffu, p, 4);
        p += __shfl_xor_sync(0xffffffffu, p, 2);
        p += __shfl_xor_sync(0xffffffffu, p, 1);
        if (n == 0) {
            float yv = p + Dv * xav;
            float zv = xz[(size_t)m * (2 * DINNER) + DINNER + e];
            y[(size_t)m * DINNER + e] = yv * siluf(zv);
        }
    }
}

// ---------------- launch ------------------------------------------------------
extern "C" void kernel_launch(void* const* d_in, const int* in_sizes, int n_in,
                              void* d_out, int out_size) {
    const int* x            = (const int*)d_in[0];
    const float* embed_W    = (const float*)d_in[1];
    const float* norm_w     = (const float*)d_in[2];
    const float* in_proj_w  = (const float*)d_in[3];
    const float* conv_w     = (const float*)d_in[4];
    const float* conv_b     = (const float*)d_in[5];
    const float* x_proj_w   = (const float*)d_in[6];
    const float* dt_proj_w  = (const float*)d_in[7];
    const float* dt_proj_b  = (const float*)d_in[8];
    const float* A_log      = (const float*)d_in[9];
    const float* D_param    = (const float*)d_in[10];
    const float* out_proj_w = (const float*)d_in[11];
    const float* normf_w    = (const float*)d_in[12];
    const float* head_w     = (const float*)d_in[13];
    const float* head_b     = (const float*)d_in[14];
    float* logits           = (float*)d_out;

    float *hbuf, *xn, *xz, *xa, *dbc, *delta, *ybuf;
    cudaGetSymbolAddress((void**)&hbuf,  g_h);
    cudaGetSymbolAddress((void**)&xn,    g_xn);
    cudaGetSymbolAddress((void**)&xz,    g_xz);
    cudaGetSymbolAddress((void**)&xa,    g_xa);
    cudaGetSymbolAddress((void**)&dbc,   g_dbc);
    cudaGetSymbolAddress((void**)&delta, g_delta);
    cudaGetSymbolAddress((void**)&ybuf,  g_y);

    embed_kernel<<<MTOK, 256>>>(x, embed_W, hbuf);

    for (int i = 0; i < NLAYERS; i++) {
        const float* nw  = norm_w     + (size_t)i * DMODEL;
        const float* iw  = in_proj_w  + (size_t)i * 2 * DINNER * DMODEL;
        const float* cw  = conv_w     + (size_t)i * DINNER * DCONV;
        const float* cb  = conv_b     + (size_t)i * DINNER;
        const float* xpw = x_proj_w   + (size_t)i * DBC_W * DINNER;
        const float* dtw = dt_proj_w  + (size_t)i * DINNER * DTRANK;
        const float* dtb = dt_proj_b  + (size_t)i * DINNER;
        const float* al  = A_log      + (size_t)i * DINNER * DSTATE;
        const float* dp  = D_param    + (size_t)i * DINNER;
        const float* ow  = out_proj_w + (size_t)i * DMODEL * DINNER;

        rmsnorm_kernel<<<MTOK, 256>>>(hbuf, nw, xn);

        // xz[2048,3072] = xn @ iw^T   (tf32 tensor cores)
        {
            dim3 grid(2 * DINNER / TBN, MTOK / TBM);
            tf32_gemm_nt<EPI_NONE><<<grid, 128>>>(MTOK, 2 * DINNER, DMODEL,
                                                  xn, DMODEL, iw, DMODEL,
                                                  xz, 2 * DINNER, nullptr, nullptr);
        }

        conv_silu_kernel<<<(MTOK * DINNER + 255) / 256, 256>>>(xz, cw, cb, xa);

        // dbc[2048,80] = xa @ xpw^T   (SIMT; N=80 too small for tile)
        {
            dim3 grid((DBC_W + GBN - 1) / GBN, (MTOK + GBM - 1) / GBM);
            sgemm_nt_simt<<<grid, 256>>>(MTOK, DBC_W, DINNER,
                                         xa, DINNER, xpw, DINNER, dbc, DBC_W);
        }

        // delta[2048,1536] = softplus(dbc[:, :48] @ dtw^T + dtb)  (tf32)
        {
            dim3 grid(DINNER / TBN, MTOK / TBM);
            tf32_gemm_nt<EPI_BIAS_SOFTPLUS><<<grid, 128>>>(MTOK, DINNER, DTRANK,
                                                           dbc, DBC_W, dtw, DTRANK,
                                                           delta, DINNER, dtb, nullptr);
        }

        // selective scan + gate
        {
            int warps = BB * (DINNER / 2);
            int blocks = (warps * 32 + 255) / 256;
            scan_kernel<<<blocks, 256>>>(delta, dbc, xa, xz, al, dp, ybuf);
        }

        // h += y @ ow^T  (tf32, residual fused)
        {
            dim3 grid(DMODEL / TBN, MTOK / TBM);
            tf32_gemm_nt<EPI_RESADD><<<grid, 128>>>(MTOK, DMODEL, DINNER,
                                                    ybuf, DINNER, ow, DINNER,
                                                    hbuf, DMODEL, nullptr, hbuf);
        }
    }

    rmsnorm_kernel<<<MTOK, 256>>>(hbuf, normf_w, xn);

    // logits = xn @ head_w^T + head_b  (tf32)
    {
        dim3 grid(VOCABN / TBN, MTOK / TBM);
        tf32_gemm_nt<EPI_BIAS><<<grid, 128>>>(MTOK, VOCABN, DMODEL,
                                              xn, DMODEL, head_w, DMODEL,
                                              logits, VOCABN, head_b, nullptr);
    }

    (void)in_sizes; (void)n_in; (void)out_size;
}

// round 4
// speedup vs baseline: 2.0948x; 1.0696x over previous
#include <cuda_runtime.h>
#include <math.h>
#include <stdint.h>

#define BB 2
#define LL 1024
#define MTOK 2048           // B*L
#define DMODEL 768
#define DINNER 1536
#define DSTATE 16
#define DTRANK 48
#define DBC_W  80
#define DCONV 4
#define VOCABN 32000
#define NLAYERS 2

// ---------------- scratch (device globals; no allocations allowed) ----------
__device__ float g_h[MTOK * DMODEL];
__device__ float g_xn[MTOK * DMODEL];
__device__ float g_xz[MTOK * 2 * DINNER];
__device__ float g_xa[MTOK * DINNER];
__device__ float g_dbc[MTOK * DBC_W];
__device__ float g_delta[MTOK * DINNER];
__device__ float g_y[MTOK * DINNER];
// tf32-RNA-rounded weight copies
__device__ float g_w_in[NLAYERS * 2 * DINNER * DMODEL];
__device__ float g_w_out[NLAYERS * DMODEL * DINNER];
__device__ float g_w_head[VOCABN * DMODEL];

// ---------------- helpers ----------------------------------------------------
__device__ __forceinline__ float softplusf(float x) {
    return (x > 20.f) ? x : log1pf(__expf(x));
}
__device__ __forceinline__ float siluf(float x) {
    return x / (1.f + __expf(-x));
}
__device__ __forceinline__ uint32_t f2tf32(float x) {
    uint32_t r;
    asm("cvt.rna.tf32.f32 %0, %1;" : "=r"(r) : "f"(x));
    return r;
}
__device__ __forceinline__ float roundtf32(float x) {
    return __uint_as_float(f2tf32(x));
}
__device__ __forceinline__ uint32_t smem_u32(const void* p) {
    return (uint32_t)__cvta_generic_to_shared(p);
}
__device__ __forceinline__ void cpa16s(uint32_t smem_dst, const void* gmem_src) {
    asm volatile("cp.async.cg.shared.global [%0], [%1], 16;" :: "r"(smem_dst), "l"(gmem_src));
}
__device__ __forceinline__ void cpa16(void* smem_dst, const void* gmem_src) {
    cpa16s(smem_u32(smem_dst), gmem_src);
}
__device__ __forceinline__ void cpa_commit() {
    asm volatile("cp.async.commit_group;");
}

// =============================================================================
// Big TF32 mma.sync GEMM: C[M,N] = A[M,K]*B[N,K]^T (K contiguous both sides).
// Inputs MUST be pre-rounded to tf32 (RNA) — hot loop feeds raw bits to mma.
// CTA tile 128x128, BK=32, 256 threads = 8 warps (warp tile 64x32), 2 CTAs/SM.
// Requires M%128==0, N%128==0, K%32==0.
// =============================================================================
#define BGM 128
#define BGN 128
#define BGK 32
#define BGLD (BGK + 4)                      // 36 floats row stride
#define BG_STAGE_FLOATS (2 * BGM * BGLD)    // A + B = 9216 floats
#define BG_SMEM_BYTES (2 * BG_STAGE_FLOATS * 4)  // 73728

#define EPI_NONE 0
#define EPI_BIAS 1
#define EPI_BIAS_SOFTPLUS 2
#define EPI_RESADD 3

__device__ __forceinline__ void bg_load(float* stageBase, int tid,
    const float* __restrict__ A, int lda, const float* __restrict__ B, int ldb,
    int mBase, int nBase, int kbase) {
    uint32_t aS = smem_u32(stageBase);
    uint32_t bS = aS + (uint32_t)(BGM * BGLD * 4);
#pragma unroll
    for (int i = 0; i < 4; i++) {
        int g = i * 256 + tid;
        int row = g >> 3, q = g & 7;
        cpa16s(aS + (uint32_t)(row * BGLD + q * 4) * 4,
               A + (size_t)(mBase + row) * lda + kbase + q * 4);
    }
#pragma unroll
    for (int i = 0; i < 4; i++) {
        int g = i * 256 + tid;
        int row = g >> 3, q = g & 7;
        cpa16s(bS + (uint32_t)(row * BGLD + q * 4) * 4,
               B + (size_t)(nBase + row) * ldb + kbase + q * 4);
    }
    cpa_commit();
}

template <int EPI>
__global__ __launch_bounds__(256, 2) void big_gemm_nt(
    int M, int N, int K,
    const float* __restrict__ A, int lda,
    const float* __restrict__ B, int ldb,
    float* __restrict__ C, int ldc,
    const float* __restrict__ bias,
    const float* __restrict__ res) {
    extern __shared__ float bsm[];

    const int tid  = threadIdx.x;
    const int warp = tid >> 5;
    const int lane = tid & 31;
    const int wm = (warp >> 2) * 64;   // 2 warp-rows
    const int wn = (warp & 3) * 32;    // 4 warp-cols
    const int g = lane >> 2;           // 0..7
    const int t = lane & 3;            // 0..3

    const int mBase = blockIdx.y * BGM;
    const int nBase = blockIdx.x * BGN;

    float acc[4][4][4];
#pragma unroll
    for (int mi = 0; mi < 4; mi++)
#pragma unroll
        for (int ni = 0; ni < 4; ni++)
#pragma unroll
            for (int c = 0; c < 4; c++) acc[mi][ni][c] = 0.f;

    const int T = K / BGK;

    bg_load(bsm, tid, A, lda, B, ldb, mBase, nBase, 0);

    const int aoff0 = (wm + g) * BGLD + t;
    const int boff0 = (wn + g) * BGLD + t;

    for (int kt = 0; kt < T; kt++) {
        if (kt + 1 < T) {
            bg_load(bsm + ((kt + 1) & 1) * BG_STAGE_FLOATS, tid,
                    A, lda, B, ldb, mBase, nBase, (kt + 1) * BGK);
            asm volatile("cp.async.wait_group 1;" ::: "memory");
        } else {
            asm volatile("cp.async.wait_group 0;" ::: "memory");
        }
        __syncthreads();

        const uint32_t* Au = (const uint32_t*)(bsm + (kt & 1) * BG_STAGE_FLOATS);
        const uint32_t* Bu = Au + BGM * BGLD;

#pragma unroll
        for (int ks = 0; ks < 4; ks++) {
            const int kb = ks * 8;
            uint32_t af[4][4];
            uint32_t bf[4][2];
#pragma unroll
            for (int mi = 0; mi < 4; mi++) {
                int base = aoff0 + mi * 16 * BGLD + kb;
                af[mi][0] = Au[base];
                af[mi][1] = Au[base + 8 * BGLD];
                af[mi][2] = Au[base + 4];
                af[mi][3] = Au[base + 8 * BGLD + 4];
            }
#pragma unroll
            for (int ni = 0; ni < 4; ni++) {
                int nb = boff0 + ni * 8 * BGLD + kb;
                bf[ni][0] = Bu[nb];
                bf[ni][1] = Bu[nb + 4];
            }
#pragma unroll
            for (int mi = 0; mi < 4; mi++)
#pragma unroll
                for (int ni = 0; ni < 4; ni++) {
                    asm volatile(
                        "mma.sync.aligned.m16n8k8.row.col.f32.tf32.tf32.f32 "
                        "{%0,%1,%2,%3}, {%4,%5,%6,%7}, {%8,%9}, {%0,%1,%2,%3};"
                        : "+f"(acc[mi][ni][0]), "+f"(acc[mi][ni][1]),
                          "+f"(acc[mi][ni][2]), "+f"(acc[mi][ni][3])
                        : "r"(af[mi][0]), "r"(af[mi][1]), "r"(af[mi][2]), "r"(af[mi][3]),
                          "r"(bf[ni][0]), "r"(bf[ni][1]));
                }
        }
        __syncthreads();
    }

    // epilogue
#pragma unroll
    for (int mi = 0; mi < 4; mi++) {
        int row = mBase + wm + mi * 16 + g;
#pragma unroll
        for (int ni = 0; ni < 4; ni++) {
            int col = nBase + wn + ni * 8 + 2 * t;
            float v0 = acc[mi][ni][0], v1 = acc[mi][ni][1];
            float v2 = acc[mi][ni][2], v3 = acc[mi][ni][3];
            if (EPI == EPI_BIAS) {
                float2 bv = *(const float2*)(bias + col);
                v0 += bv.x; v1 += bv.y; v2 += bv.x; v3 += bv.y;
            }
            if (EPI == EPI_RESADD) {
                float2 r0 = *(const float2*)(res + (size_t)row * ldc + col);
                float2 r1 = *(const float2*)(res + (size_t)(row + 8) * ldc + col);
                v0 += r0.x; v1 += r0.y; v2 += r1.x; v3 += r1.y;
            }
            *(float2*)(C + (size_t)row * ldc + col) = make_float2(v0, v1);
            *(float2*)(C + (size_t)(row + 8) * ldc + col) = make_float2(v2, v3);
        }
    }
}

// ---------------- tf32 RNA rounding pass (weights) ---------------------------
__global__ void round_tf32_kernel(const float* __restrict__ in,
                                  float* __restrict__ out, int n4) {
    int i = blockIdx.x * blockDim.x + threadIdx.x;
    if (i >= n4) return;
    float4 v = ((const float4*)in)[i];
    v.x = roundtf32(v.x); v.y = roundtf32(v.y);
    v.z = roundtf32(v.z); v.w = roundtf32(v.w);
    ((float4*)out)[i] = v;
}

// ---------------- embedding gather -------------------------------------------
__global__ void embed_kernel(const int* __restrict__ tok,
                             const float* __restrict__ W,
                             float* __restrict__ out) {
    int m = blockIdx.x;
    int t = tok[m];
    const float* src = W + (size_t)t * DMODEL;
    float* dst = out + (size_t)m * DMODEL;
    for (int i = threadIdx.x; i < DMODEL; i += blockDim.x) dst[i] = src[i];
}

// ---------------- rmsnorm (output rounded to tf32) ---------------------------
__global__ void rmsnorm_kernel(const float* __restrict__ x,
                               const float* __restrict__ w,
                               float* __restrict__ out) {
    int m = blockIdx.x;
    const float* row = x + (size_t)m * DMODEL;
    float s = 0.f;
    for (int i = threadIdx.x; i < DMODEL; i += blockDim.x) {
        float v = row[i];
        s += v * v;
    }
    for (int o = 16; o > 0; o >>= 1) s += __shfl_xor_sync(0xffffffffu, s, o);
    __shared__ float red[8];
    __shared__ float scale_s;
    int warp = threadIdx.x >> 5, lane = threadIdx.x & 31;
    if (lane == 0) red[warp] = s;
    __syncthreads();
    if (threadIdx.x == 0) {
        float t = 0.f;
        int nw = (blockDim.x + 31) >> 5;
        for (int i = 0; i < nw; i++) t += red[i];
        scale_s = rsqrtf(t / (float)DMODEL + 1e-5f);
    }
    __syncthreads();
    float scale = scale_s;
    for (int i = threadIdx.x; i < DMODEL; i += blockDim.x)
        out[(size_t)m * DMODEL + i] = roundtf32(row[i] * scale * w[i]);
}

// ---------------- warp-MMA tf32 GEMM (kept for delta: K=48) ------------------
#define TBM 128
#define TBN 128
#define TBK 16
#define TPAD 4
#define TKS (TBK + TPAD)

template <int EPI>
__global__ __launch_bounds__(128) void tf32_gemm_nt(
    int M, int N, int K,
    const float* __restrict__ A, int lda,
    const float* __restrict__ B, int ldb,
    float* __restrict__ C, int ldc,
    const float* __restrict__ bias,
    const float* __restrict__ res) {
    __shared__ float As[2][TBM][TKS];
    __shared__ float Bs[2][TBN][TKS];

    const int tid  = threadIdx.x;
    const int warp = tid >> 5;
    const int lane = tid & 31;
    const int wm = (warp >> 1) * 64;
    const int wn = (warp & 1) * 64;
    const int g = lane >> 2;
    const int t = lane & 3;

    const int mBase = blockIdx.y * TBM;
    const int nBase = blockIdx.x * TBN;

    const float* Abase = A + (size_t)mBase * lda;
    const float* Bbase = B + (size_t)nBase * ldb;

    const int lr = tid >> 2;
    const int lk = (tid & 3) * 4;

    float acc[4][8][4];
#pragma unroll
    for (int mi = 0; mi < 4; mi++)
#pragma unroll
        for (int ni = 0; ni < 8; ni++)
#pragma unroll
            for (int c = 0; c < 4; c++) acc[mi][ni][c] = 0.f;

    const int T = K / TBK;
    {
#pragma unroll
        for (int i = 0; i < 4; i++) {
            int row = lr + i * 32;
            cpa16(&As[0][row][lk], Abase + (size_t)row * lda + lk);
            cpa16(&Bs[0][row][lk], Bbase + (size_t)row * ldb + lk);
        }
        cpa_commit();
    }

    for (int kt = 0; kt < T; kt++) {
        if (kt + 1 < T) {
            int k0 = (kt + 1) * TBK;
            int buf = (kt + 1) & 1;
#pragma unroll
            for (int i = 0; i < 4; i++) {
                int row = lr + i * 32;
                cpa16(&As[buf][row][lk], Abase + (size_t)row * lda + k0 + lk);
                cpa16(&Bs[buf][row][lk], Bbase + (size_t)row * ldb + k0 + lk);
            }
            cpa_commit();
            asm volatile("cp.async.wait_group 1;");
        } else {
            asm volatile("cp.async.wait_group 0;");
        }
        __syncthreads();

        const int buf = kt & 1;
#pragma unroll
        for (int ks = 0; ks < 2; ks++) {
            const int kb = ks * 8;
            uint32_t af[4][4];
            uint32_t bf[8][2];
#pragma unroll
            for (int mi = 0; mi < 4; mi++) {
                int m = wm + mi * 16;
                af[mi][0] = f2tf32(As[buf][m + g][kb + t]);
                af[mi][1] = f2tf32(As[buf][m + g + 8][kb + t]);
                af[mi][2] = f2tf32(As[buf][m + g][kb + t + 4]);
                af[mi][3] = f2tf32(As[buf][m + g + 8][kb + t + 4]);
            }
#pragma unroll
            for (int ni = 0; ni < 8; ni++) {
                int n = wn + ni * 8;
                bf[ni][0] = f2tf32(Bs[buf][n + g][kb + t]);
                bf[ni][1] = f2tf32(Bs[buf][n + g][kb + t + 4]);
            }
#pragma unroll
            for (int mi = 0; mi < 4; mi++)
#pragma unroll
                for (int ni = 0; ni < 8; ni++) {
                    asm volatile(
                        "mma.sync.aligned.m16n8k8.row.col.f32.tf32.tf32.f32 "
                        "{%0,%1,%2,%3}, {%4,%5,%6,%7}, {%8,%9}, {%0,%1,%2,%3};"
                        : "+f"(acc[mi][ni][0]), "+f"(acc[mi][ni][1]),
                          "+f"(acc[mi][ni][2]), "+f"(acc[mi][ni][3])
                        : "r"(af[mi][0]), "r"(af[mi][1]), "r"(af[mi][2]), "r"(af[mi][3]),
                          "r"(bf[ni][0]), "r"(bf[ni][1]));
                }
        }
        __syncthreads();
    }

#pragma unroll
    for (int mi = 0; mi < 4; mi++) {
        int row = mBase + wm + mi * 16 + g;
#pragma unroll
        for (int ni = 0; ni < 8; ni++) {
            int col = nBase + wn + ni * 8 + 2 * t;
            float v0 = acc[mi][ni][0], v1 = acc[mi][ni][1];
            float v2 = acc[mi][ni][2], v3 = acc[mi][ni][3];
            if (EPI == EPI_BIAS_SOFTPLUS) {
                float2 bv = *(const float2*)(bias + col);
                v0 = softplusf(v0 + bv.x); v1 = softplusf(v1 + bv.y);
                v2 = softplusf(v2 + bv.x); v3 = softplusf(v3 + bv.y);
            }
            *(float2*)(C + (size_t)row * ldc + col) = make_float2(v0, v1);
            *(float2*)(C + (size_t)(row + 8) * ldc + col) = make_float2(v2, v3);
        }
    }
    (void)res;
}

// ---------------- SIMT SGEMM (dbc: N=80) -------------------------------------
#define GBM 128
#define GBN 128
#define GBK 8
#define GTM 8
#define GTN 8

__global__ __launch_bounds__(256) void sgemm_nt_simt(
    int M, int N, int K,
    const float* __restrict__ A, int lda,
    const float* __restrict__ B, int ldb,
    float* __restrict__ C, int ldc) {
    __shared__ float As[GBK][GBM];
    __shared__ float Bs[GBK][GBN];

    const int tid = threadIdx.x;
    const int tcol = tid & 15;
    const int trow = tid >> 4;

    const int mBase = blockIdx.y * GBM;
    const int nBase = blockIdx.x * GBN;

    const float* Ab = A + (size_t)mBase * lda;
    const float* Bb = B + (size_t)nBase * ldb;

    const int lrow = tid >> 1;
    const int lcol = (tid & 1) * 4;

    const bool aRowValid = (mBase + lrow) < M;
    const bool bRowValid = (nBase + lrow) < N;

    float acc[GTM][GTN];
#pragma unroll
    for (int i = 0; i < GTM; i++)
#pragma unroll
        for (int j = 0; j < GTN; j++) acc[i][j] = 0.f;

    for (int k0 = 0; k0 < K; k0 += GBK) {
        float4 a4 = make_float4(0.f, 0.f, 0.f, 0.f);
        float4 b4 = make_float4(0.f, 0.f, 0.f, 0.f);
        if (aRowValid && (k0 + lcol) < K)
            a4 = *(const float4*)(Ab + (size_t)lrow * lda + k0 + lcol);
        if (bRowValid && (k0 + lcol) < K)
            b4 = *(const float4*)(Bb + (size_t)lrow * ldb + k0 + lcol);
        As[lcol + 0][lrow] = a4.x; As[lcol + 1][lrow] = a4.y;
        As[lcol + 2][lrow] = a4.z; As[lcol + 3][lrow] = a4.w;
        Bs[lcol + 0][lrow] = b4.x; Bs[lcol + 1][lrow] = b4.y;
        Bs[lcol + 2][lrow] = b4.z; Bs[lcol + 3][lrow] = b4.w;
        __syncthreads();

#pragma unroll
        for (int k = 0; k < GBK; k++) {
            float regM[GTM], regN[GTN];
#pragma unroll
            for (int i = 0; i < GTM; i++) regM[i] = As[k][trow * GTM + i];
#pragma unroll
            for (int j = 0; j < GTN; j++) regN[j] = Bs[k][tcol * GTN + j];
#pragma unroll
            for (int i = 0; i < GTM; i++)
#pragma unroll
                for (int j = 0; j < GTN; j++)
                    acc[i][j] = fmaf(regM[i], regN[j], acc[i][j]);
        }
        __syncthreads();
    }

#pragma unroll
    for (int i = 0; i < GTM; i++) {
        int row = mBase + trow * GTM + i;
        if (row >= M) continue;
#pragma unroll
        for (int j = 0; j < GTN; j++) {
            int col = nBase + tcol * GTN + j;
            if (col >= N) continue;
            C[(size_t)row * ldc + col] = acc[i][j];
        }
    }
}

// ---------------- causal depthwise conv + bias + SiLU ------------------------
__global__ void conv_silu_kernel(const float* __restrict__ xz,
                                 const float* __restrict__ cw,
                                 const float* __restrict__ cb,
                                 float* __restrict__ xa) {
    int idx = blockIdx.x * blockDim.x + threadIdx.x;
    if (idx >= MTOK * DINNER) return;
    int e = idx % DINNER;
    int m = idx / DINNER;
    int l = m % LL;
    float acc = cb[e];
#pragma unroll
    for (int j = 0; j < DCONV; j++) {
        int lj = l + j - (DCONV - 1);
        if (lj >= 0)
            acc = fmaf(xz[(size_t)(m + j - (DCONV - 1)) * (2 * DINNER) + e],
                       cw[e * DCONV + j], acc);
    }
    xa[idx] = siluf(acc);
}

// ---------------- selective scan + gate (output rounded to tf32) -------------
__global__ void scan_kernel(const float* __restrict__ delta,
                            const float* __restrict__ dbc,
                            const float* __restrict__ xa,
                            const float* __restrict__ xz,
                            const float* __restrict__ A_log,
                            const float* __restrict__ Dp,
                            float* __restrict__ y) {
    int w = (blockIdx.x * blockDim.x + threadIdx.x) >> 5;
    int lane = threadIdx.x & 31;
    if (w >= BB * (DINNER / 2)) return;
    int b = w / (DINNER / 2);
    int ep = w % (DINNER / 2);
    int half = lane >> 4;
    int n = lane & 15;
    int e = ep * 2 + half;

    float A_ne = -__expf(A_log[e * DSTATE + n]);
    float Dv = Dp[e];
    float h = 0.f;
    int m0 = b * LL;
    for (int l = 0; l < LL; l++) {
        int m = m0 + l;
        float dlt = delta[(size_t)m * DINNER + e];
        float xav = xa[(size_t)m * DINNER + e];
        float Bv = dbc[(size_t)m * DBC_W + DTRANK + n];
        float Cv = dbc[(size_t)m * DBC_W + DTRANK + DSTATE + n];
        float dA = __expf(dlt * A_ne);
        h = fmaf(dA, h, dlt * Bv * xav);
        float p = h * Cv;
        p += __shfl_xor_sync(0xffffffffu, p, 8);
        p += __shfl_xor_sync(0xffffffffu, p, 4);
        p += __shfl_xor_sync(0xffffffffu, p, 2);
        p += __shfl_xor_sync(0xffffffffu, p, 1);
        if (n == 0) {
            float yv = p + Dv * xav;
            float zv = xz[(size_t)m * (2 * DINNER) + DINNER + e];
            y[(size_t)m * DINNER + e] = roundtf32(yv * siluf(zv));
        }
    }
}

// ---------------- launch ------------------------------------------------------
extern "C" void kernel_launch(void* const* d_in, const int* in_sizes, int n_in,
                              void* d_out, int out_size) {
    const int* x            = (const int*)d_in[0];
    const float* embed_W    = (const float*)d_in[1];
    const float* norm_w     = (const float*)d_in[2];
    const float* in_proj_w  = (const float*)d_in[3];
    const float* conv_w     = (const float*)d_in[4];
    const float* conv_b     = (const float*)d_in[5];
    const float* x_proj_w   = (const float*)d_in[6];
    const float* dt_proj_w  = (const float*)d_in[7];
    const float* dt_proj_b  = (const float*)d_in[8];
    const float* A_log      = (const float*)d_in[9];
    const float* D_param    = (const float*)d_in[10];
    const float* out_proj_w = (const float*)d_in[11];
    const float* normf_w    = (const float*)d_in[12];
    const float* head_w     = (const float*)d_in[13];
    const float* head_b     = (const float*)d_in[14];
    float* logits           = (float*)d_out;

    float *hbuf, *xn, *xz, *xa, *dbc, *delta, *ybuf;
    float *wr_in, *wr_out, *wr_head;
    cudaGetSymbolAddress((void**)&hbuf,  g_h);
    cudaGetSymbolAddress((void**)&xn,    g_xn);
    cudaGetSymbolAddress((void**)&xz,    g_xz);
    cudaGetSymbolAddress((void**)&xa,    g_xa);
    cudaGetSymbolAddress((void**)&dbc,   g_dbc);
    cudaGetSymbolAddress((void**)&delta, g_delta);
    cudaGetSymbolAddress((void**)&ybuf,  g_y);
    cudaGetSymbolAddress((void**)&wr_in,   g_w_in);
    cudaGetSymbolAddress((void**)&wr_out,  g_w_out);
    cudaGetSymbolAddress((void**)&wr_head, g_w_head);

    cudaFuncSetAttribute(big_gemm_nt<EPI_NONE>,
                         cudaFuncAttributeMaxDynamicSharedMemorySize, BG_SMEM_BYTES);
    cudaFuncSetAttribute(big_gemm_nt<EPI_BIAS>,
                         cudaFuncAttributeMaxDynamicSharedMemorySize, BG_SMEM_BYTES);
    cudaFuncSetAttribute(big_gemm_nt<EPI_RESADD>,
                         cudaFuncAttributeMaxDynamicSharedMemorySize, BG_SMEM_BYTES);

    // weight rounding (RNA tf32)
    {
        int n4 = NLAYERS * 2 * DINNER * DMODEL / 4;
        round_tf32_kernel<<<(n4 + 255) / 256, 256>>>(in_proj_w, wr_in, n4);
        n4 = NLAYERS * DMODEL * DINNER / 4;
        round_tf32_kernel<<<(n4 + 255) / 256, 256>>>(out_proj_w, wr_out, n4);
        n4 = VOCABN * DMODEL / 4;
        round_tf32_kernel<<<(n4 + 255) / 256, 256>>>(head_w, wr_head, n4);
    }

    embed_kernel<<<MTOK, 256>>>(x, embed_W, hbuf);

    for (int i = 0; i < NLAYERS; i++) {
        const float* nw  = norm_w     + (size_t)i * DMODEL;
        const float* iw  = wr_in      + (size_t)i * 2 * DINNER * DMODEL;
        const float* cw  = conv_w     + (size_t)i * DINNER * DCONV;
        const float* cb  = conv_b     + (size_t)i * DINNER;
        const float* xpw = x_proj_w   + (size_t)i * DBC_W * DINNER;
        const float* dtw = dt_proj_w  + (size_t)i * DINNER * DTRANK;
        const float* dtb = dt_proj_b  + (size_t)i * DINNER;
        const float* al  = A_log      + (size_t)i * DINNER * DSTATE;
        const float* dp  = D_param    + (size_t)i * DINNER;
        const float* ow  = wr_out     + (size_t)i * DMODEL * DINNER;

        rmsnorm_kernel<<<MTOK, 256>>>(hbuf, nw, xn);

        // xz = xn @ iw^T
        {
            dim3 grid(2 * DINNER / BGN, MTOK / BGM);
            big_gemm_nt<EPI_NONE><<<grid, 256, BG_SMEM_BYTES>>>(
                MTOK, 2 * DINNER, DMODEL, xn, DMODEL, iw, DMODEL,
                xz, 2 * DINNER, nullptr, nullptr);
        }

        conv_silu_kernel<<<(MTOK * DINNER + 255) / 256, 256>>>(xz, cw, cb, xa);

        // dbc = xa @ xpw^T  (SIMT, N=80)
        {
            dim3 grid(1, MTOK / GBM);
            sgemm_nt_simt<<<grid, 256>>>(MTOK, DBC_W, DINNER,
                                         xa, DINNER, xpw, DINNER, dbc, DBC_W);
        }

        // delta = softplus(dbc[:, :48] @ dtw^T + dtb)  (warp-MMA, K=48, cvt in-loop)
        {
            dim3 grid(DINNER / TBN, MTOK / TBM);
            tf32_gemm_nt<EPI_BIAS_SOFTPLUS><<<grid, 128>>>(
                MTOK, DINNER, DTRANK, dbc, DBC_W, dtw, DTRANK,
                delta, DINNER, dtb, nullptr);
        }

        // selective scan + gate
        {
            int warps = BB * (DINNER / 2);
            int blocks = (warps * 32 + 255) / 256;
            scan_kernel<<<blocks, 256>>>(delta, dbc, xa, xz, al, dp, ybuf);
        }

        // h += y @ ow^T  (residual fused)
        {
            dim3 grid(DMODEL / BGN, MTOK / BGM);
            big_gemm_nt<EPI_RESADD><<<grid, 256, BG_SMEM_BYTES>>>(
                MTOK, DMODEL, DINNER, ybuf, DINNER, ow, DINNER,
                hbuf, DMODEL, nullptr, hbuf);
        }
    }

    rmsnorm_kernel<<<MTOK, 256>>>(hbuf, normf_w, xn);

    // logits = xn @ head_w^T + head_b
    {
        dim3 grid(VOCABN / BGN, MTOK / BGM);
        big_gemm_nt<EPI_BIAS><<<grid, 256, BG_SMEM_BYTES>>>(
            MTOK, VOCABN, DMODEL, xn, DMODEL, wr_head, DMODEL,
            logits, VOCABN, head_b, nullptr);
    }

    (void)in_sizes; (void)n_in; (void)out_size;
}

// round 5
// speedup vs baseline: 2.9352x; 1.4012x over previous
#include <cuda_runtime.h>
#include <cuda_fp16.h>
#include <math.h>
#include <stdint.h>

#define BB 2
#define LL 1024
#define MTOK 2048           // B*L
#define DMODEL 768
#define DINNER 1536
#define DSTATE 16
#define DTRANK 48
#define DBC_W  80
#define DCONV 4
#define VOCABN 32000
#define NLAYERS 2

// ---------------- scratch (device globals; no allocations allowed) ----------
__device__ float g_h[MTOK * DMODEL];
__device__ float g_xz[MTOK * 2 * DINNER];
__device__ float g_xa[MTOK * DINNER];
__device__ float g_dbc[MTOK * DBC_W];
__device__ float g_delta[MTOK * DINNER];
__device__ __half g_xn_h[MTOK * DMODEL];
__device__ __half g_y_h[MTOK * DINNER];
// fp16 weight copies
__device__ __half g_hw_in[NLAYERS * 2 * DINNER * DMODEL];
__device__ __half g_hw_out[NLAYERS * DMODEL * DINNER];
__device__ __half g_hw_head[VOCABN * DMODEL];

// ---------------- helpers ----------------------------------------------------
__device__ __forceinline__ float softplusf(float x) {
    return (x > 20.f) ? x : log1pf(__expf(x));
}
__device__ __forceinline__ float siluf(float x) {
    return x / (1.f + __expf(-x));
}
__device__ __forceinline__ uint32_t f2tf32(float x) {
    uint32_t r;
    asm("cvt.rna.tf32.f32 %0, %1;" : "=r"(r) : "f"(x));
    return r;
}
__device__ __forceinline__ uint32_t smem_u32(const void* p) {
    return (uint32_t)__cvta_generic_to_shared(p);
}
__device__ __forceinline__ void cpa16s(uint32_t smem_dst, const void* gmem_src) {
    asm volatile("cp.async.cg.shared.global [%0], [%1], 16;" :: "r"(smem_dst), "l"(gmem_src));
}
__device__ __forceinline__ void cpa16(void* smem_dst, const void* gmem_src) {
    cpa16s(smem_u32(smem_dst), gmem_src);
}
__device__ __forceinline__ void cpa_commit() {
    asm volatile("cp.async.commit_group;");
}

// =============================================================================
// FP16 mma.sync GEMM: C[M,N](f32) = A[M,K](f16) * B[N,K](f16)^T.
// CTA 128x128, BK=64, 256 threads = 8 warps (warp tile 64x32), 2 CTAs/SM.
// Requires M%128==0, N%128==0, K%64==0.
// =============================================================================
#define HGM 128
#define HGN 128
#define HGK 64
#define HLD 72                               // halfs per smem row (64 + 8 pad)
#define HG_STAGE_HALFS (256 * HLD)           // A(128 rows) + B(128 rows)
#define HG_SMEM_BYTES (2 * HG_STAGE_HALFS * 2)   // 73728

#define EPI_NONE 0
#define EPI_BIAS 1
#define EPI_RESADD 3

__device__ __forceinline__ void hg_load(__half* stage, int tid,
    const __half* __restrict__ A, int lda, const __half* __restrict__ B, int ldb,
    int mBase, int nBase, int kbase) {
    uint32_t aS = smem_u32(stage);
    uint32_t bS = aS + (uint32_t)(128 * HLD * 2);
#pragma unroll
    for (int i = 0; i < 4; i++) {
        int g = i * 256 + tid;              // 0..1023
        int row = g >> 3, q = g & 7;        // row 0..127, q 0..7 (8 halfs each)
        cpa16s(aS + (uint32_t)(row * HLD + q * 8) * 2,
               A + (size_t)(mBase + row) * lda + kbase + q * 8);
    }
#pragma unroll
    for (int i = 0; i < 4; i++) {
        int g = i * 256 + tid;
        int row = g >> 3, q = g & 7;
        cpa16s(bS + (uint32_t)(row * HLD + q * 8) * 2,
               B + (size_t)(nBase + row) * ldb + kbase + q * 8);
    }
    cpa_commit();
}

template <int EPI>
__global__ __launch_bounds__(256, 2) void hgemm_nt(
    int M, int N, int K,
    const __half* __restrict__ A, int lda,
    const __half* __restrict__ B, int ldb,
    float* __restrict__ C, int ldc,
    const float* __restrict__ bias,
    const float* __restrict__ res) {
    extern __shared__ __half hsm[];

    const int tid  = threadIdx.x;
    const int warp = tid >> 5;
    const int lane = tid & 31;
    const int wm = (warp >> 2) * 64;
    const int wn = (warp & 3) * 32;
    const int g = lane >> 2;    // 0..7
    const int t = lane & 3;     // 0..3

    const int mBase = blockIdx.y * HGM;
    const int nBase = blockIdx.x * HGN;

    float acc[4][4][4];
#pragma unroll
    for (int mi = 0; mi < 4; mi++)
#pragma unroll
        for (int ni = 0; ni < 4; ni++)
#pragma unroll
            for (int c = 0; c < 4; c++) acc[mi][ni][c] = 0.f;

    const int T = K / HGK;

    hg_load(hsm, tid, A, lda, B, ldb, mBase, nBase, 0);

    // u32 indices into smem (2 halfs per u32); row stride = HLD/2 = 36
    const int aoff0 = (wm + g) * 36 + t;
    const int boff0 = (128 + wn + g) * 36 + t;

    for (int kt = 0; kt < T; kt++) {
        if (kt + 1 < T) {
            hg_load(hsm + ((kt + 1) & 1) * HG_STAGE_HALFS, tid,
                    A, lda, B, ldb, mBase, nBase, (kt + 1) * HGK);
            asm volatile("cp.async.wait_group 1;" ::: "memory");
        } else {
            asm volatile("cp.async.wait_group 0;" ::: "memory");
        }
        __syncthreads();

        const uint32_t* Su = (const uint32_t*)(hsm + (kt & 1) * HG_STAGE_HALFS);

#pragma unroll
        for (int ks = 0; ks < 4; ks++) {       // 4 k-steps of 16
            const int kb2 = ks * 8;            // u32 offset within row
            uint32_t af[4][4];
            uint32_t bf[4][2];
#pragma unroll
            for (int mi = 0; mi < 4; mi++) {
                int base = aoff0 + mi * 16 * 36 + kb2;
                af[mi][0] = Su[base];
                af[mi][1] = Su[base + 8 * 36];
                af[mi][2] = Su[base + 4];
                af[mi][3] = Su[base + 8 * 36 + 4];
            }
#pragma unroll
            for (int ni = 0; ni < 4; ni++) {
                int nb = boff0 + ni * 8 * 36 + kb2;
                bf[ni][0] = Su[nb];
                bf[ni][1] = Su[nb + 4];
            }
#pragma unroll
            for (int mi = 0; mi < 4; mi++)
#pragma unroll
                for (int ni = 0; ni < 4; ni++) {
                    asm volatile(
                        "mma.sync.aligned.m16n8k16.row.col.f32.f16.f16.f32 "
                        "{%0,%1,%2,%3}, {%4,%5,%6,%7}, {%8,%9}, {%0,%1,%2,%3};"
                        : "+f"(acc[mi][ni][0]), "+f"(acc[mi][ni][1]),
                          "+f"(acc[mi][ni][2]), "+f"(acc[mi][ni][3])
                        : "r"(af[mi][0]), "r"(af[mi][1]), "r"(af[mi][2]), "r"(af[mi][3]),
                          "r"(bf[ni][0]), "r"(bf[ni][1]));
                }
        }
        __syncthreads();
    }

    // epilogue (acc layout: c0,c1 @ row g cols 2t,2t+1; c2,c3 @ row g+8)
#pragma unroll
    for (int mi = 0; mi < 4; mi++) {
        int row = mBase + wm + mi * 16 + g;
#pragma unroll
        for (int ni = 0; ni < 4; ni++) {
            int col = nBase + wn + ni * 8 + 2 * t;
            float v0 = acc[mi][ni][0], v1 = acc[mi][ni][1];
            float v2 = acc[mi][ni][2], v3 = acc[mi][ni][3];
            if (EPI == EPI_BIAS) {
                float2 bv = *(const float2*)(bias + col);
                v0 += bv.x; v1 += bv.y; v2 += bv.x; v3 += bv.y;
            }
            if (EPI == EPI_RESADD) {
                float2 r0 = *(const float2*)(res + (size_t)row * ldc + col);
                float2 r1 = *(const float2*)(res + (size_t)(row + 8) * ldc + col);
                v0 += r0.x; v1 += r0.y; v2 += r1.x; v3 += r1.y;
            }
            *(float2*)(C + (size_t)row * ldc + col) = make_float2(v0, v1);
            *(float2*)(C + (size_t)(row + 8) * ldc + col) = make_float2(v2, v3);
        }
    }
}

// ---------------- fp32 -> fp16 convert pass ----------------------------------
__global__ void f2h_kernel(const float* __restrict__ in,
                           __half* __restrict__ out, int n4) {
    int i = blockIdx.x * blockDim.x + threadIdx.x;
    if (i >= n4) return;
    float4 v = ((const float4*)in)[i];
    __half2 h0 = __floats2half2_rn(v.x, v.y);
    __half2 h1 = __floats2half2_rn(v.z, v.w);
    ((__half2*)out)[i * 2]     = h0;
    ((__half2*)out)[i * 2 + 1] = h1;
}

// ---------------- zero pass ---------------------------------------------------
__global__ void zero_kernel(float* __restrict__ p, int n) {
    int i = blockIdx.x * blockDim.x + threadIdx.x;
    if (i < n) p[i] = 0.f;
}

// ---------------- embedding gather -------------------------------------------
__global__ void embed_kernel(const int* __restrict__ tok,
                             const float* __restrict__ W,
                             float* __restrict__ out) {
    int m = blockIdx.x;
    int t = tok[m];
    const float* src = W + (size_t)t * DMODEL;
    float* dst = out + (size_t)m * DMODEL;
    for (int i = threadIdx.x; i < DMODEL; i += blockDim.x) dst[i] = src[i];
}

// ---------------- rmsnorm (emits fp16) ----------------------------------------
__global__ void rmsnorm_kernel(const float* __restrict__ x,
                               const float* __restrict__ w,
                               __half* __restrict__ out) {
    int m = blockIdx.x;
    const float* row = x + (size_t)m * DMODEL;
    float s = 0.f;
    for (int i = threadIdx.x; i < DMODEL; i += blockDim.x) {
        float v = row[i];
        s += v * v;
    }
    for (int o = 16; o > 0; o >>= 1) s += __shfl_xor_sync(0xffffffffu, s, o);
    __shared__ float red[8];
    __shared__ float scale_s;
    int warp = threadIdx.x >> 5, lane = threadIdx.x & 31;
    if (lane == 0) red[warp] = s;
    __syncthreads();
    if (threadIdx.x == 0) {
        float t = 0.f;
        int nw = (blockDim.x + 31) >> 5;
        for (int i = 0; i < nw; i++) t += red[i];
        scale_s = rsqrtf(t / (float)DMODEL + 1e-5f);
    }
    __syncthreads();
    float scale = scale_s;
    for (int i = threadIdx.x; i < DMODEL; i += blockDim.x)
        out[(size_t)m * DMODEL + i] = __float2half(row[i] * scale * w[i]);
}

// ---------------- warp-MMA tf32 GEMM (delta: K=48) ----------------------------
#define TBM 128
#define TBN 128
#define TBK 16
#define TPAD 4
#define TKS (TBK + TPAD)

__global__ __launch_bounds__(128) void delta_gemm(
    int M, int N, int K,
    const float* __restrict__ A, int lda,
    const float* __restrict__ B, int ldb,
    float* __restrict__ C, int ldc,
    const float* __restrict__ bias) {
    __shared__ float As[2][TBM][TKS];
    __shared__ float Bs[2][TBN][TKS];

    const int tid  = threadIdx.x;
    const int warp = tid >> 5;
    const int lane = tid & 31;
    const int wm = (warp >> 1) * 64;
    const int wn = (warp & 1) * 64;
    const int g = lane >> 2;
    const int t = lane & 3;

    const int mBase = blockIdx.y * TBM;
    const int nBase = blockIdx.x * TBN;

    const float* Abase = A + (size_t)mBase * lda;
    const float* Bbase = B + (size_t)nBase * ldb;

    const int lr = tid >> 2;
    const int lk = (tid & 3) * 4;

    float acc[4][8][4];
#pragma unroll
    for (int mi = 0; mi < 4; mi++)
#pragma unroll
        for (int ni = 0; ni < 8; ni++)
#pragma unroll
            for (int c = 0; c < 4; c++) acc[mi][ni][c] = 0.f;

    const int T = K / TBK;
    {
#pragma unroll
        for (int i = 0; i < 4; i++) {
            int row = lr + i * 32;
            cpa16(&As[0][row][lk], Abase + (size_t)row * lda + lk);
            cpa16(&Bs[0][row][lk], Bbase + (size_t)row * ldb + lk);
        }
        cpa_commit();
    }

    for (int kt = 0; kt < T; kt++) {
        if (kt + 1 < T) {
            int k0 = (kt + 1) * TBK;
            int buf = (kt + 1) & 1;
#pragma unroll
            for (int i = 0; i < 4; i++) {
                int row = lr + i * 32;
                cpa16(&As[buf][row][lk], Abase + (size_t)row * lda + k0 + lk);
                cpa16(&Bs[buf][row][lk], Bbase + (size_t)row * ldb + k0 + lk);
            }
            cpa_commit();
            asm volatile("cp.async.wait_group 1;");
        } else {
            asm volatile("cp.async.wait_group 0;");
        }
        __syncthreads();

        const int buf = kt & 1;
#pragma unroll
        for (int ks = 0; ks < 2; ks++) {
            const int kb = ks * 8;
            uint32_t af[4][4];
            uint32_t bf[8][2];
#pragma unroll
            for (int mi = 0; mi < 4; mi++) {
                int m = wm + mi * 16;
                af[mi][0] = f2tf32(As[buf][m + g][kb + t]);
                af[mi][1] = f2tf32(As[buf][m + g + 8][kb + t]);
                af[mi][2] = f2tf32(As[buf][m + g][kb + t + 4]);
                af[mi][3] = f2tf32(As[buf][m + g + 8][kb + t + 4]);
            }
#pragma unroll
            for (int ni = 0; ni < 8; ni++) {
                int n = wn + ni * 8;
                bf[ni][0] = f2tf32(Bs[buf][n + g][kb + t]);
                bf[ni][1] = f2tf32(Bs[buf][n + g][kb + t + 4]);
            }
#pragma unroll
            for (int mi = 0; mi < 4; mi++)
#pragma unroll
                for (int ni = 0; ni < 8; ni++) {
                    asm volatile(
                        "mma.sync.aligned.m16n8k8.row.col.f32.tf32.tf32.f32 "
                        "{%0,%1,%2,%3}, {%4,%5,%6,%7}, {%8,%9}, {%0,%1,%2,%3};"
                        : "+f"(acc[mi][ni][0]), "+f"(acc[mi][ni][1]),
                          "+f"(acc[mi][ni][2]), "+f"(acc[mi][ni][3])
                        : "r"(af[mi][0]), "r"(af[mi][1]), "r"(af[mi][2]), "r"(af[mi][3]),
                          "r"(bf[ni][0]), "r"(bf[ni][1]));
                }
        }
        __syncthreads();
    }

#pragma unroll
    for (int mi = 0; mi < 4; mi++) {
        int row = mBase + wm + mi * 16 + g;
#pragma unroll
        for (int ni = 0; ni < 8; ni++) {
            int col = nBase + wn + ni * 8 + 2 * t;
            float2 bv = *(const float2*)(bias + col);
            float v0 = softplusf(acc[mi][ni][0] + bv.x);
            float v1 = softplusf(acc[mi][ni][1] + bv.y);
            float v2 = softplusf(acc[mi][ni][2] + bv.x);
            float v3 = softplusf(acc[mi][ni][3] + bv.y);
            *(float2*)(C + (size_t)row * ldc + col) = make_float2(v0, v1);
            *(float2*)(C + (size_t)(row + 8) * ldc + col) = make_float2(v2, v3);
        }
    }
}

// ---------------- SIMT split-K GEMM for dbc (N=80) ----------------------------
#define DBC_SPLITK 8
#define DBC_KC (DINNER / DBC_SPLITK)   // 192
#define GBM 128
#define GBK 8

__global__ __launch_bounds__(256) void dbc_gemm_splitk(
    const float* __restrict__ A, int lda,
    const float* __restrict__ B, int ldb,
    float* __restrict__ C, int ldc) {
    __shared__ float As[GBK][GBM];
    __shared__ float Bs[GBK][GBM];

    const int tid = threadIdx.x;
    const int tcol = tid & 15;
    const int trow = tid >> 4;

    const int mBase = blockIdx.y * GBM;
    const int kBase = blockIdx.x * DBC_KC;

    const float* Ab = A + (size_t)mBase * lda;

    const int lrow = tid >> 1;
    const int lcol = (tid & 1) * 4;
    const bool bRowValid = lrow < DBC_W;

    float acc[8][8];
#pragma unroll
    for (int i = 0; i < 8; i++)
#pragma unroll
        for (int j = 0; j < 8; j++) acc[i][j] = 0.f;

    for (int k0 = kBase; k0 < kBase + DBC_KC; k0 += GBK) {
        float4 a4 = *(const float4*)(Ab + (size_t)lrow * lda + k0 + lcol);
        float4 b4 = make_float4(0.f, 0.f, 0.f, 0.f);
        if (bRowValid)
            b4 = *(const float4*)(B + (size_t)lrow * ldb + k0 + lcol);
        As[lcol + 0][lrow] = a4.x; As[lcol + 1][lrow] = a4.y;
        As[lcol + 2][lrow] = a4.z; As[lcol + 3][lrow] = a4.w;
        Bs[lcol + 0][lrow] = b4.x; Bs[lcol + 1][lrow] = b4.y;
        Bs[lcol + 2][lrow] = b4.z; Bs[lcol + 3][lrow] = b4.w;
        __syncthreads();

#pragma unroll
        for (int k = 0; k < GBK; k++) {
            float regM[8], regN[8];
#pragma unroll
            for (int i = 0; i < 8; i++) regM[i] = As[k][trow * 8 + i];
#pragma unroll
            for (int j = 0; j < 8; j++) regN[j] = Bs[k][tcol * 8 + j];
#pragma unroll
            for (int i = 0; i < 8; i++)
#pragma unroll
                for (int j = 0; j < 8; j++)
                    acc[i][j] = fmaf(regM[i], regN[j], acc[i][j]);
        }
        __syncthreads();
    }

#pragma unroll
    for (int i = 0; i < 8; i++) {
        int row = mBase + trow * 8 + i;
#pragma unroll
        for (int j = 0; j < 8; j++) {
            int col = tcol * 8 + j;
            if (col < DBC_W)
                atomicAdd(&C[(size_t)row * ldc + col], acc[i][j]);
        }
    }
}

// ---------------- causal depthwise conv + bias + SiLU ------------------------
__global__ void conv_silu_kernel(const float* __restrict__ xz,
                                 const float* __restrict__ cw,
                                 const float* __restrict__ cb,
                                 float* __restrict__ xa) {
    int idx = blockIdx.x * blockDim.x + threadIdx.x;
    if (idx >= MTOK * DINNER) return;
    int e = idx % DINNER;
    int m = idx / DINNER;
    int l = m % LL;
    float acc = cb[e];
#pragma unroll
    for (int j = 0; j < DCONV; j++) {
        int lj = l + j - (DCONV - 1);
        if (lj >= 0)
            acc = fmaf(xz[(size_t)(m + j - (DCONV - 1)) * (2 * DINNER) + e],
                       cw[e * DCONV + j], acc);
    }
    xa[idx] = siluf(acc);
}

// ---------------- selective scan + gate (emits fp16) --------------------------
__global__ void scan_kernel(const float* __restrict__ delta,
                            const float* __restrict__ dbc,
                            const float* __restrict__ xa,
                            const float* __restrict__ xz,
                            const float* __restrict__ A_log,
                            const float* __restrict__ Dp,
                            __half* __restrict__ y) {
    int w = (blockIdx.x * blockDim.x + threadIdx.x) >> 5;
    int lane = threadIdx.x & 31;
    if (w >= BB * (DINNER / 2)) return;
    int b = w / (DINNER / 2);
    int ep = w % (DINNER / 2);
    int half = lane >> 4;
    int n = lane & 15;
    int e = ep * 2 + half;

    float A_ne = -__expf(A_log[e * DSTATE + n]);
    float Dv = Dp[e];
    float h = 0.f;
    int m0 = b * LL;
    for (int l = 0; l < LL; l++) {
        int m = m0 + l;
        float dlt = delta[(size_t)m * DINNER + e];
        float xav = xa[(size_t)m * DINNER + e];
        float Bv = dbc[(size_t)m * DBC_W + DTRANK + n];
        float Cv = dbc[(size_t)m * DBC_W + DTRANK + DSTATE + n];
        float dA = __expf(dlt * A_ne);
        h = fmaf(dA, h, dlt * Bv * xav);
        float p = h * Cv;
        p += __shfl_xor_sync(0xffffffffu, p, 8);
        p += __shfl_xor_sync(0xffffffffu, p, 4);
        p += __shfl_xor_sync(0xffffffffu, p, 2);
        p += __shfl_xor_sync(0xffffffffu, p, 1);
        if (n == 0) {
            float yv = p + Dv * xav;
            float zv = xz[(size_t)m * (2 * DINNER) + DINNER + e];
            y[(size_t)m * DINNER + e] = __float2half(yv * siluf(zv));
        }
    }
}

// ---------------- launch ------------------------------------------------------
extern "C" void kernel_launch(void* const* d_in, const int* in_sizes, int n_in,
                              void* d_out, int out_size) {
    const int* x            = (const int*)d_in[0];
    const float* embed_W    = (const float*)d_in[1];
    const float* norm_w     = (const float*)d_in[2];
    const float* in_proj_w  = (const float*)d_in[3];
    const float* conv_w     = (const float*)d_in[4];
    const float* conv_b     = (const float*)d_in[5];
    const float* x_proj_w   = (const float*)d_in[6];
    const float* dt_proj_w  = (const float*)d_in[7];
    const float* dt_proj_b  = (const float*)d_in[8];
    const float* A_log      = (const float*)d_in[9];
    const float* D_param    = (const float*)d_in[10];
    const float* out_proj_w = (const float*)d_in[11];
    const float* normf_w    = (const float*)d_in[12];
    const float* head_w     = (const float*)d_in[13];
    const float* head_b     = (const float*)d_in[14];
    float* logits           = (float*)d_out;

    float *hbuf, *xz, *xa, *dbc, *delta;
    __half *xn_h, *y_h, *hw_in, *hw_out, *hw_head;
    cudaGetSymbolAddress((void**)&hbuf,  g_h);
    cudaGetSymbolAddress((void**)&xz,    g_xz);
    cudaGetSymbolAddress((void**)&xa,    g_xa);
    cudaGetSymbolAddress((void**)&dbc,   g_dbc);
    cudaGetSymbolAddress((void**)&delta, g_delta);
    cudaGetSymbolAddress((void**)&xn_h,  g_xn_h);
    cudaGetSymbolAddress((void**)&y_h,   g_y_h);
    cudaGetSymbolAddress((void**)&hw_in,   g_hw_in);
    cudaGetSymbolAddress((void**)&hw_out,  g_hw_out);
    cudaGetSymbolAddress((void**)&hw_head, g_hw_head);

    cudaFuncSetAttribute(hgemm_nt<EPI_NONE>,
                         cudaFuncAttributeMaxDynamicSharedMemorySize, HG_SMEM_BYTES);
    cudaFuncSetAttribute(hgemm_nt<EPI_BIAS>,
                         cudaFuncAttributeMaxDynamicSharedMemorySize, HG_SMEM_BYTES);
    cudaFuncSetAttribute(hgemm_nt<EPI_RESADD>,
                         cudaFuncAttributeMaxDynamicSharedMemorySize, HG_SMEM_BYTES);

    // weight conversion to fp16
    {
        int n4 = NLAYERS * 2 * DINNER * DMODEL / 4;
        f2h_kernel<<<(n4 + 255) / 256, 256>>>(in_proj_w, hw_in, n4);
        n4 = NLAYERS * DMODEL * DINNER / 4;
        f2h_kernel<<<(n4 + 255) / 256, 256>>>(out_proj_w, hw_out, n4);
        n4 = VOCABN * DMODEL / 4;
        f2h_kernel<<<(n4 + 255) / 256, 256>>>(head_w, hw_head, n4);
    }

    embed_kernel<<<MTOK, 256>>>(x, embed_W, hbuf);

    for (int i = 0; i < NLAYERS; i++) {
        const float* nw  = norm_w     + (size_t)i * DMODEL;
        const __half* iw = hw_in      + (size_t)i * 2 * DINNER * DMODEL;
        const float* cw  = conv_w     + (size_t)i * DINNER * DCONV;
        const float* cb  = conv_b     + (size_t)i * DINNER;
        const float* xpw = x_proj_w   + (size_t)i * DBC_W * DINNER;
        const float* dtw = dt_proj_w  + (size_t)i * DINNER * DTRANK;
        const float* dtb = dt_proj_b  + (size_t)i * DINNER;
        const float* al  = A_log      + (size_t)i * DINNER * DSTATE;
        const float* dp  = D_param    + (size_t)i * DINNER;
        const __half* ow = hw_out     + (size_t)i * DMODEL * DINNER;

        rmsnorm_kernel<<<MTOK, 256>>>(hbuf, nw, xn_h);

        // xz = xn @ iw^T   (fp16 mma)
        {
            dim3 grid(2 * DINNER / HGN, MTOK / HGM);
            hgemm_nt<EPI_NONE><<<grid, 256, HG_SMEM_BYTES>>>(
                MTOK, 2 * DINNER, DMODEL, xn_h, DMODEL, iw, DMODEL,
                xz, 2 * DINNER, nullptr, nullptr);
        }

        conv_silu_kernel<<<(MTOK * DINNER + 255) / 256, 256>>>(xz, cw, cb, xa);

        // dbc = xa @ xpw^T  (SIMT split-K, N=80)
        zero_kernel<<<(MTOK * DBC_W + 255) / 256, 256>>>(dbc, MTOK * DBC_W);
        {
            dim3 grid(DBC_SPLITK, MTOK / GBM);
            dbc_gemm_splitk<<<grid, 256>>>(xa, DINNER, xpw, DINNER, dbc, DBC_W);
        }

        // delta = softplus(dbc[:, :48] @ dtw^T + dtb)
        {
            dim3 grid(DINNER / TBN, MTOK / TBM);
            delta_gemm<<<grid, 128>>>(MTOK, DINNER, DTRANK,
                                      dbc, DBC_W, dtw, DTRANK,
                                      delta, DINNER, dtb);
        }

        // selective scan + gate -> fp16 y
        {
            int warps = BB * (DINNER / 2);
            int blocks = (warps * 32 + 255) / 256;
            scan_kernel<<<blocks, 256>>>(delta, dbc, xa, xz, al, dp, y_h);
        }

        // h += y @ ow^T  (fp16 mma, residual fused)
        {
            dim3 grid(DMODEL / HGN, MTOK / HGM);
            hgemm_nt<EPI_RESADD><<<grid, 256, HG_SMEM_BYTES>>>(
                MTOK, DMODEL, DINNER, y_h, DINNER, ow, DINNER,
                hbuf, DMODEL, nullptr, hbuf);
        }
    }

    rmsnorm_kernel<<<MTOK, 256>>>(hbuf, normf_w, xn_h);

    // logits = xn @ head_w^T + head_b  (fp16 mma)
    {
        dim3 grid(VOCABN / HGN, MTOK / HGM);
        hgemm_nt<EPI_BIAS><<<grid, 256, HG_SMEM_BYTES>>>(
            MTOK, VOCABN, DMODEL, xn_h, DMODEL, hw_head, DMODEL,
            logits, VOCABN, head_b, nullptr);
    }

    (void)in_sizes; (void)n_in; (void)out_size;
}